// round 3
// baseline (speedup 1.0000x reference)
#include <cuda_runtime.h>
#include <cstdint>

// Problem constants (fixed shapes per reference setup_inputs)
constexpr int NN   = 50000;    // batch_size * num_nodes
constexpr int NE   = 800000;   // edges
constexpr int DIM  = 128;      // D_IN == D_OUT

// Scratch: segment sums + counts (device globals; no allocation)
__device__ __align__(16) float g_sum[(size_t)NN * DIM];
__device__ float g_cnt[NN];
__device__ int   g_is64;       // 1 if edge_index buffer is int64, 0 if int32

// ---------------------------------------------------------------------------
// Kernel 1: zero accumulators + detect edge_index dtype.
// int64 data interpreted as int64 -> all values in [0, NN).
// int32 data interpreted as int64 -> lo + hi*2^32, out of range immediately.
// ---------------------------------------------------------------------------
__global__ void __launch_bounds__(256) zero_detect_kernel(const void* __restrict__ ei) {
    int i = blockIdx.x * blockDim.x + threadIdx.x;
    constexpr int n4 = NN * DIM / 4;   // 1,600,000 float4
    if (i < n4) reinterpret_cast<float4*>(g_sum)[i] = make_float4(0.f, 0.f, 0.f, 0.f);
    if (i < NN) g_cnt[i] = 0.f;
    if (i == 0) {
        const long long* p = (const long long*)ei;
        int ok = 1;
        for (int k = 0; k < 1024; k++) {
            long long v = p[k];
            if (v < 0 || v >= NN) { ok = 0; break; }
        }
        g_is64 = ok;
    }
}

// ---------------------------------------------------------------------------
// Kernel 2: edge scatter. One warp per edge; lane l handles cols [4l,4l+4).
// Vectorized reduction red.global.add.v4.f32 (sm_90+) quarters atomic issue.
// ---------------------------------------------------------------------------
__global__ void __launch_bounds__(256) scatter_kernel(const float* __restrict__ x,
                                                      const void* __restrict__ ei) {
    long long idx = (long long)blockIdx.x * blockDim.x + threadIdx.x;
    int e = (int)(idx >> 5);
    if (e >= NE) return;
    int lane = (int)(idx & 31);

    int r, c;
    if (g_is64) {
        const long long* p = (const long long*)ei;
        r = (int)p[e];
        c = (int)p[NE + e];
    } else {
        const int* p = (const int*)ei;
        r = p[e];
        c = p[NE + e];
    }
    if ((unsigned)r >= (unsigned)NN || (unsigned)c >= (unsigned)NN) return;

    float4 v = reinterpret_cast<const float4*>(x + (size_t)c * DIM)[lane];
    float* dst = g_sum + (size_t)r * DIM + lane * 4;
    asm volatile("red.global.add.v4.f32 [%0], {%1, %2, %3, %4};"
                 :: "l"(dst), "f"(v.x), "f"(v.y), "f"(v.z), "f"(v.w)
                 : "memory");
    if (lane == 0) atomicAdd(&g_cnt[r], 1.0f);
}

// ---------------------------------------------------------------------------
// Kernel 3: mean + GEMM.  out[r][o] = (sum[r]/max(cnt[r],1)) . W[o] + b[o]
// Block: 256 threads, tile 128 rows x 128 cols, 8x8 register tile per thread.
// K tiled by 32 so static smem stays under 48KB (2 * 32*132*4 = 33.8 KB).
// smem stored K-major with pad 132 so both m and w read as aligned float4.
// ---------------------------------------------------------------------------
constexpr int KT  = 32;
constexpr int PAD = 132;

__global__ void __launch_bounds__(256) mean_gemm_kernel(const float* __restrict__ W,
                                                        const float* __restrict__ bias,
                                                        float* __restrict__ out) {
    __shared__ float sW[KT * PAD];   // sW[kk*PAD + o]  = W[o][kt+kk]
    __shared__ float sM[KT * PAD];   // sM[kk*PAD + rl] = mean[row0+rl][kt+kk]

    const int tid = threadIdx.x;
    const int tc  = tid & 15;        // column group: cols [tc*8, tc*8+8)
    const int tr  = tid >> 4;        // row group:    rows [tr*8, tr*8+8)
    const int row0 = blockIdx.x * 128;

    float acc[8][8];
#pragma unroll
    for (int i = 0; i < 8; i++)
#pragma unroll
        for (int j = 0; j < 8; j++) acc[i][j] = 0.f;

    for (int kt = 0; kt < DIM; kt += KT) {
        // Load W tile (transposed into K-major). Coalesced gmem reads.
#pragma unroll
        for (int i = tid; i < KT * DIM; i += 256) {
            int o  = i >> 5;
            int kk = i & 31;
            sW[kk * PAD + o] = W[o * DIM + kt + kk];
        }
        // Load mean tile (transposed into K-major), fusing count division.
#pragma unroll
        for (int i = tid; i < KT * DIM; i += 256) {
            int rl = i >> 5;
            int kk = i & 31;
            int row = row0 + rl;
            float v = 0.f;
            if (row < NN) {
                float cnt = g_cnt[row];
                v = g_sum[(size_t)row * DIM + kt + kk] * (1.0f / fmaxf(cnt, 1.0f));
            }
            sM[kk * PAD + rl] = v;
        }
        __syncthreads();

#pragma unroll 8
        for (int kk = 0; kk < KT; kk++) {
            float4 w0 = *reinterpret_cast<const float4*>(&sW[kk * PAD + tc * 8]);
            float4 w1 = *reinterpret_cast<const float4*>(&sW[kk * PAD + tc * 8 + 4]);
            float4 m0 = *reinterpret_cast<const float4*>(&sM[kk * PAD + tr * 8]);
            float4 m1 = *reinterpret_cast<const float4*>(&sM[kk * PAD + tr * 8 + 4]);
            float wv[8] = {w0.x, w0.y, w0.z, w0.w, w1.x, w1.y, w1.z, w1.w};
            float mv[8] = {m0.x, m0.y, m0.z, m0.w, m1.x, m1.y, m1.z, m1.w};
#pragma unroll
            for (int i = 0; i < 8; i++)
#pragma unroll
                for (int j = 0; j < 8; j++)
                    acc[i][j] = fmaf(mv[i], wv[j], acc[i][j]);
        }
        __syncthreads();
    }

    float bj[8];
#pragma unroll
    for (int j = 0; j < 8; j++) bj[j] = bias[tc * 8 + j];

#pragma unroll
    for (int i = 0; i < 8; i++) {
        int row = row0 + tr * 8 + i;
        if (row < NN) {
            float4 o0 = make_float4(acc[i][0] + bj[0], acc[i][1] + bj[1],
                                    acc[i][2] + bj[2], acc[i][3] + bj[3]);
            float4 o1 = make_float4(acc[i][4] + bj[4], acc[i][5] + bj[5],
                                    acc[i][6] + bj[6], acc[i][7] + bj[7]);
            float4* dst = reinterpret_cast<float4*>(out + (size_t)row * DIM + tc * 8);
            dst[0] = o0;
            dst[1] = o1;
        }
    }
}

// ---------------------------------------------------------------------------
// Launch. Inputs resolved by element count (robust to scalar args placement):
//   x: 6,400,000 f32 | edge_index: 1,600,000 elems (i32 or i64) |
//   W: 16,384 f32 | b: 128 f32
// ---------------------------------------------------------------------------
extern "C" void kernel_launch(void* const* d_in, const int* in_sizes, int n_in,
                              void* d_out, int out_size) {
    const float* x = nullptr;
    const void*  ei = nullptr;
    const float* W = nullptr;
    const float* b = nullptr;

    for (int i = 0; i < n_in; i++) {
        switch (in_sizes[i]) {
            case NN * DIM:    if (!x)  x  = (const float*)d_in[i]; break;
            case 2 * NE:      if (!ei) ei = d_in[i];               break;
            case DIM * DIM:   if (!W)  W  = (const float*)d_in[i]; break;
            case DIM:         if (!b)  b  = (const float*)d_in[i]; break;
            default: break;
        }
    }

    float* out = (float*)d_out;

    // 1) zero accumulators + dtype detection
    {
        constexpr int n4 = NN * DIM / 4;
        int threads = n4 > NN ? n4 : NN;
        zero_detect_kernel<<<(threads + 255) / 256, 256>>>(ei);
    }
    // 2) edge scatter (one warp per edge)
    {
        long long total = (long long)NE * 32;
        int blocks = (int)((total + 255) / 256);
        scatter_kernel<<<blocks, 256>>>(x, ei);
    }
    // 3) mean + GEMM
    {
        int blocks = (NN + 127) / 128;   // 391
        mean_gemm_kernel<<<blocks, 256>>>(W, b, out);
    }
}

// round 4
// speedup vs baseline: 1.7271x; 1.7271x over previous
#include <cuda_runtime.h>
#include <cstdint>

// Problem constants (fixed shapes per reference setup_inputs)
constexpr int NN   = 50000;    // batch_size * num_nodes
constexpr int NE   = 800000;   // edges
constexpr int DIM  = 128;      // D_IN == D_OUT

constexpr int CHUNK   = 512;
constexpr int NCHUNKS = (NN + CHUNK - 1) / CHUNK;   // 98

// Scratch (device globals; no allocation)
__device__ int g_cnt[NN];          // per-row degree
__device__ int g_row_start[NN];    // CSR offsets
__device__ int g_cursor[NN];       // fill cursors (copy of row_start)
__device__ int g_chunk_sum[NCHUNKS];
__device__ int g_chunk_off[NCHUNKS];
__device__ int g_bucket[NE];       // source node per edge, bucketed by dest
__device__ __align__(16) float g_mean[(size_t)NN * DIM];
__device__ int g_is64;             // 1 if edge_index is int64, 0 if int32

// ---------------------------------------------------------------------------
// K1: zero degree counters + detect edge_index dtype.
// int64 data read as int64 -> all values in [0, NN); int32 data read as
// int64 packs two indices per word -> out of range immediately.
// ---------------------------------------------------------------------------
__global__ void __launch_bounds__(256) init_kernel(const void* __restrict__ ei) {
    int i = blockIdx.x * blockDim.x + threadIdx.x;
    if (i < NN) g_cnt[i] = 0;
    if (i == 0) {
        const long long* p = (const long long*)ei;
        int ok = 1;
        for (int k = 0; k < 1024; k++) {
            long long v = p[k];
            if (v < 0 || v >= NN) { ok = 0; break; }
        }
        g_is64 = ok;
    }
}

// ---------------------------------------------------------------------------
// K2: histogram of destination rows (int atomics, spread addresses)
// ---------------------------------------------------------------------------
__global__ void __launch_bounds__(256) hist_kernel(const void* __restrict__ ei) {
    int e = blockIdx.x * blockDim.x + threadIdx.x;
    if (e >= NE) return;
    int r = g_is64 ? (int)((const long long*)ei)[e] : ((const int*)ei)[e];
    if ((unsigned)r < (unsigned)NN) atomicAdd(&g_cnt[r], 1);
}

// ---------------------------------------------------------------------------
// K3: per-chunk degree sums (98 chunks of 512)
// ---------------------------------------------------------------------------
__global__ void __launch_bounds__(256) chunk_reduce_kernel() {
    __shared__ int s[256];
    int blk = blockIdx.x;
    int t = threadIdx.x;
    int base = blk * CHUNK;
    int v = 0;
    int i0 = base + t;
    int i1 = base + t + 256;
    if (i0 < NN) v += g_cnt[i0];
    if (i1 < NN) v += g_cnt[i1];
    s[t] = v;
    __syncthreads();
    for (int off = 128; off > 0; off >>= 1) {
        if (t < off) s[t] += s[t + off];
        __syncthreads();
    }
    if (t == 0) g_chunk_sum[blk] = s[0];
}

// ---------------------------------------------------------------------------
// K4: exclusive scan of 98 chunk sums (single block, serial in smem)
// ---------------------------------------------------------------------------
__global__ void __launch_bounds__(128) chunk_scan_kernel() {
    __shared__ int s[NCHUNKS];
    int t = threadIdx.x;
    if (t < NCHUNKS) s[t] = g_chunk_sum[t];
    __syncthreads();
    if (t == 0) {
        int run = 0;
        for (int k = 0; k < NCHUNKS; k++) {
            int v = s[k];
            s[k] = run;
            run += v;
        }
    }
    __syncthreads();
    if (t < NCHUNKS) g_chunk_off[t] = s[t];
}

// ---------------------------------------------------------------------------
// K5: per-chunk exclusive scan -> row_start, cursor (512 threads per chunk)
// ---------------------------------------------------------------------------
__global__ void __launch_bounds__(512) row_scan_kernel() {
    __shared__ int s[CHUNK];
    int blk = blockIdx.x;
    int t = threadIdx.x;
    int i = blk * CHUNK + t;
    int v = (i < NN) ? g_cnt[i] : 0;
    s[t] = v;
    __syncthreads();
    // Hillis-Steele inclusive scan
    for (int off = 1; off < CHUNK; off <<= 1) {
        int add = (t >= off) ? s[t - off] : 0;
        __syncthreads();
        s[t] += add;
        __syncthreads();
    }
    if (i < NN) {
        int start = g_chunk_off[blk] + s[t] - v;   // exclusive
        g_row_start[i] = start;
        g_cursor[i] = start;
    }
}

// ---------------------------------------------------------------------------
// K6: bucket fill — scatter source indices into CSR order
// ---------------------------------------------------------------------------
__global__ void __launch_bounds__(256) fill_kernel(const void* __restrict__ ei) {
    int e = blockIdx.x * blockDim.x + threadIdx.x;
    if (e >= NE) return;
    int r, c;
    if (g_is64) {
        const long long* p = (const long long*)ei;
        r = (int)p[e];
        c = (int)p[NE + e];
    } else {
        const int* p = (const int*)ei;
        r = p[e];
        c = p[NE + e];
    }
    if ((unsigned)r >= (unsigned)NN || (unsigned)c >= (unsigned)NN) return;
    int pos = atomicAdd(&g_cursor[r], 1);
    g_bucket[pos] = c;
}

// ---------------------------------------------------------------------------
// K7: aggregate — one warp per destination row. Register accumulators,
// pure L2 reads, mean division fused. No float atomics anywhere.
// Lane l covers cols [4l, 4l+4) as one float4.
// ---------------------------------------------------------------------------
__global__ void __launch_bounds__(256) aggregate_kernel(const float* __restrict__ x) {
    int warp = (blockIdx.x * blockDim.x + threadIdx.x) >> 5;
    if (warp >= NN) return;
    int lane = threadIdx.x & 31;

    int base = g_row_start[warp];
    int deg  = g_cnt[warp];

    float4 acc = make_float4(0.f, 0.f, 0.f, 0.f);
    for (int i0 = 0; i0 < deg; i0 += 32) {
        int n = min(32, deg - i0);
        int c = (i0 + lane < deg) ? g_bucket[base + i0 + lane] : 0;  // coalesced
#pragma unroll 4
        for (int j = 0; j < n; j++) {
            int cj = __shfl_sync(0xffffffffu, c, j);
            float4 v = reinterpret_cast<const float4*>(x + (size_t)cj * DIM)[lane];
            acc.x += v.x; acc.y += v.y; acc.z += v.z; acc.w += v.w;
        }
    }
    float inv = 1.0f / fmaxf((float)deg, 1.0f);
    acc.x *= inv; acc.y *= inv; acc.z *= inv; acc.w *= inv;
    reinterpret_cast<float4*>(g_mean + (size_t)warp * DIM)[lane] = acc;
}

// ---------------------------------------------------------------------------
// K8: GEMM.  out[r][o] = mean[r] . W[o] + b[o]
// 256 threads, 128x128 tile, 8x8 register tile, KT=32 (smem < 48KB).
// ---------------------------------------------------------------------------
constexpr int KT  = 32;
constexpr int PAD = 132;

__global__ void __launch_bounds__(256) gemm_kernel(const float* __restrict__ W,
                                                   const float* __restrict__ bias,
                                                   float* __restrict__ out) {
    __shared__ float sW[KT * PAD];   // sW[kk*PAD + o]  = W[o][kt+kk]
    __shared__ float sM[KT * PAD];   // sM[kk*PAD + rl] = mean[row0+rl][kt+kk]

    const int tid = threadIdx.x;
    const int tc  = tid & 15;        // cols [tc*8, tc*8+8)
    const int tr  = tid >> 4;        // rows [tr*8, tr*8+8)
    const int row0 = blockIdx.x * 128;

    float acc[8][8];
#pragma unroll
    for (int i = 0; i < 8; i++)
#pragma unroll
        for (int j = 0; j < 8; j++) acc[i][j] = 0.f;

    for (int kt = 0; kt < DIM; kt += KT) {
#pragma unroll
        for (int i = tid; i < KT * DIM; i += 256) {
            int o  = i >> 5;
            int kk = i & 31;
            sW[kk * PAD + o] = W[o * DIM + kt + kk];
        }
#pragma unroll
        for (int i = tid; i < KT * DIM; i += 256) {
            int rl = i >> 5;
            int kk = i & 31;
            int row = row0 + rl;
            sM[kk * PAD + rl] = (row < NN) ? g_mean[(size_t)row * DIM + kt + kk] : 0.f;
        }
        __syncthreads();

#pragma unroll 8
        for (int kk = 0; kk < KT; kk++) {
            float4 w0 = *reinterpret_cast<const float4*>(&sW[kk * PAD + tc * 8]);
            float4 w1 = *reinterpret_cast<const float4*>(&sW[kk * PAD + tc * 8 + 4]);
            float4 m0 = *reinterpret_cast<const float4*>(&sM[kk * PAD + tr * 8]);
            float4 m1 = *reinterpret_cast<const float4*>(&sM[kk * PAD + tr * 8 + 4]);
            float wv[8] = {w0.x, w0.y, w0.z, w0.w, w1.x, w1.y, w1.z, w1.w};
            float mv[8] = {m0.x, m0.y, m0.z, m0.w, m1.x, m1.y, m1.z, m1.w};
#pragma unroll
            for (int i = 0; i < 8; i++)
#pragma unroll
                for (int j = 0; j < 8; j++)
                    acc[i][j] = fmaf(mv[i], wv[j], acc[i][j]);
        }
        __syncthreads();
    }

    float bj[8];
#pragma unroll
    for (int j = 0; j < 8; j++) bj[j] = bias[tc * 8 + j];

#pragma unroll
    for (int i = 0; i < 8; i++) {
        int row = row0 + tr * 8 + i;
        if (row < NN) {
            float4 o0 = make_float4(acc[i][0] + bj[0], acc[i][1] + bj[1],
                                    acc[i][2] + bj[2], acc[i][3] + bj[3]);
            float4 o1 = make_float4(acc[i][4] + bj[4], acc[i][5] + bj[5],
                                    acc[i][6] + bj[6], acc[i][7] + bj[7]);
            float4* dst = reinterpret_cast<float4*>(out + (size_t)row * DIM + tc * 8);
            dst[0] = o0;
            dst[1] = o1;
        }
    }
}

// ---------------------------------------------------------------------------
// Launch chain. Inputs resolved by element count.
// ---------------------------------------------------------------------------
extern "C" void kernel_launch(void* const* d_in, const int* in_sizes, int n_in,
                              void* d_out, int out_size) {
    const float* x = nullptr;
    const void*  ei = nullptr;
    const float* W = nullptr;
    const float* b = nullptr;

    for (int i = 0; i < n_in; i++) {
        switch (in_sizes[i]) {
            case NN * DIM:    if (!x)  x  = (const float*)d_in[i]; break;
            case 2 * NE:      if (!ei) ei = d_in[i];               break;
            case DIM * DIM:   if (!W)  W  = (const float*)d_in[i]; break;
            case DIM:         if (!b)  b  = (const float*)d_in[i]; break;
            default: break;
        }
    }
    float* out = (float*)d_out;

    init_kernel<<<(NN + 255) / 256, 256>>>(ei);
    hist_kernel<<<(NE + 255) / 256, 256>>>(ei);
    chunk_reduce_kernel<<<NCHUNKS, 256>>>();
    chunk_scan_kernel<<<1, 128>>>();
    row_scan_kernel<<<NCHUNKS, 512>>>();
    fill_kernel<<<(NE + 255) / 256, 256>>>(ei);
    aggregate_kernel<<<(NN * 32 + 255) / 256, 256>>>(x);
    gemm_kernel<<<(NN + 127) / 128, 256>>>(W, b, out);
}